// round 3
// baseline (speedup 1.0000x reference)
#include <cuda_runtime.h>
#include <math.h>

// Problem shape (fixed by setup_inputs)
#define NB 2
#define LL 2048
#define HH 8
#define DD 64
#define MM 64
#define NH (NB*HH)          // 16
#define T  64               // chunk length
#define CC (LL/T)           // 32 chunks
#define NBLK (NH*CC)        // 512
#define EPSF 1e-6f

// Scratch: per (head, chunk) partial sums. Static device arrays (no runtime alloc).
__device__ float g_S[(size_t)NH*CC*DD*MM];   // 8 MB: chunk-sum / exclusive-prefix of K^T V
__device__ float g_k[(size_t)NH*CC*DD];      // chunk-sum / exclusive-prefix of sum(phi(K))

__device__ __forceinline__ float phi(float x) {
    // elu(x)+1: x>0 -> x+1 ; x<=0 -> exp(x)
    return x > 0.0f ? x + 1.0f : expf(x);
}
__device__ __forceinline__ float4 phi4(float4 a) {
    return make_float4(phi(a.x), phi(a.y), phi(a.z), phi(a.w));
}

// ---------------------------------------------------------------------------
// Kernel A: per-chunk sums  Schunk[d][m] = sum_t phi(k)[t][d] * v[t][m],
//                           ksum[d]     = sum_t phi(k)[t][d]
// grid = 512 blocks (nh, c), 128 threads
// ---------------------------------------------------------------------------
__global__ void __launch_bounds__(128) chunk_sums_kernel(
    const float* __restrict__ keys, const float* __restrict__ values)
{
    __shared__ float Ks[T*DD];   // 16 KB
    __shared__ float Vs[T*MM];   // 16 KB

    const int b   = blockIdx.x;
    const int nh  = b / CC, c = b % CC;
    const int n   = nh / HH, h = nh % HH;
    const int tid = threadIdx.x;

    const float4* kg = (const float4*)keys;
    const float4* vg = (const float4*)values;
    float4* Ks4 = (float4*)Ks;
    float4* Vs4 = (float4*)Vs;

    // load chunk (coalesced, 64B rows per t), apply feature map to K
    #pragma unroll
    for (int f = tid; f < T*DD/4; f += 128) {
        int t = f >> 4;            // 16 float4 per row of D=64
        int d4 = f & 15;
        long gi = ((long)(n*LL + c*T + t)*HH + h)*(DD/4) + d4;
        Ks4[f] = phi4(kg[gi]);
        Vs4[f] = vg[gi];           // M == D, same indexing
    }
    __syncthreads();

    const int dh = tid & 1;        // which half of D
    const int m  = tid >> 1;       // output column

    float acc[32];
    #pragma unroll
    for (int j = 0; j < 32; j++) acc[j] = 0.0f;

    const float4* KK = (const float4*)Ks;
    for (int t = 0; t < T; t++) {
        float v = Vs[t*MM + m];
        #pragma unroll
        for (int jj = 0; jj < 8; jj++) {
            float4 k4 = KK[t*16 + dh*8 + jj];
            acc[jj*4+0] += k4.x * v;
            acc[jj*4+1] += k4.y * v;
            acc[jj*4+2] += k4.z * v;
            acc[jj*4+3] += k4.w * v;
        }
    }

    float* So = &g_S[(size_t)b * DD * MM];
    #pragma unroll
    for (int j = 0; j < 32; j++)
        So[(dh*32 + j)*MM + m] = acc[j];

    if (tid < DD) {
        float s = 0.0f;
        for (int t = 0; t < T; t++) s += Ks[t*DD + tid];
        g_k[(size_t)b*DD + tid] = s;
    }
}

// ---------------------------------------------------------------------------
// Kernel B: in-place exclusive prefix over chunks per head.
// grid = 16 blocks (one per nh), 1024 threads (one float4 of S each)
// ---------------------------------------------------------------------------
__global__ void __launch_bounds__(1024) prefix_kernel()
{
    const int nh  = blockIdx.x;
    const int tid = threadIdx.x;

    float4 run = make_float4(0.f, 0.f, 0.f, 0.f);
    float  runk = 0.0f;

    for (int c = 0; c < CC; c++) {
        float4* p = (float4*)&g_S[(size_t)(nh*CC + c) * DD * MM];
        float4 cur = p[tid];
        p[tid] = run;
        run.x += cur.x; run.y += cur.y; run.z += cur.z; run.w += cur.w;
        if (tid < DD) {
            float* pk = &g_k[(size_t)(nh*CC + c)*DD];
            float ck = pk[tid];
            pk[tid] = runk;
            runk += ck;
        }
    }
}

// ---------------------------------------------------------------------------
// Kernel C: in-chunk sequential scan with register-resident state columns.
// grid = 512 blocks (nh, c), 128 threads. Dynamic smem: 66 KB.
// ---------------------------------------------------------------------------
__global__ void __launch_bounds__(128) scan_kernel(
    const float* __restrict__ queries, const float* __restrict__ keys,
    const float* __restrict__ values, float* __restrict__ out)
{
    extern __shared__ float sm[];
    float* Qs   = sm;               // 4096 floats
    float* Ks   = sm + 4096;        // 4096
    float* Vs   = sm + 8192;        // 4096
    float* kcum = sm + 12288;       // 4096
    float* zinv = sm + 16384;       // 64
    float* kpre = sm + 16448;       // 64

    const int b   = blockIdx.x;
    const int nh  = b / CC, c = b % CC;
    const int n   = nh / HH, h = nh % HH;
    const int tid = threadIdx.x;

    const float4* qg = (const float4*)queries;
    const float4* kg = (const float4*)keys;
    const float4* vg = (const float4*)values;
    float4* Qs4 = (float4*)Qs;
    float4* Ks4 = (float4*)Ks;
    float4* Vs4 = (float4*)Vs;

    #pragma unroll
    for (int f = tid; f < T*DD/4; f += 128) {
        int t = f >> 4;
        int d4 = f & 15;
        long gi = ((long)(n*LL + c*T + t)*HH + h)*(DD/4) + d4;
        Qs4[f] = phi4(qg[gi]);
        Ks4[f] = phi4(kg[gi]);
        Vs4[f] = vg[gi];
    }
    if (tid < DD) kpre[tid] = g_k[(size_t)b*DD + tid];
    __syncthreads();

    // Build inclusive kcum table (threads 0..63, one d each)
    if (tid < DD) {
        float kc = kpre[tid];
        for (int i = 0; i < T; i++) {
            kc += Ks[i*DD + tid];
            kcum[i*DD + tid] = kc;
        }
    }
    __syncthreads();

    // zinv[i] = 1 / (phi(q_i) . kcum_i + eps)   (threads 0..63, one i each)
    if (tid < T) {
        const float4* qr = (const float4*)&Qs[tid*DD];
        const float4* kr = (const float4*)&kcum[tid*DD];
        float z = 0.0f;
        #pragma unroll
        for (int d4 = 0; d4 < 16; d4++) {
            float4 a = qr[d4], bb = kr[d4];
            z += a.x*bb.x + a.y*bb.y + a.z*bb.z + a.w*bb.w;
        }
        zinv[tid] = 1.0f / (z + EPSF);
    }
    __syncthreads();

    // Register-resident state: thread (m, dh) owns S[dh*32 .. dh*32+31][m]
    const int dh = tid & 1;
    const int m  = tid >> 1;

    float acc[32];
    const float* Sp = &g_S[(size_t)b * DD * MM];
    #pragma unroll
    for (int j = 0; j < 32; j++)
        acc[j] = Sp[(dh*32 + j)*MM + m];

    const float4* KK = (const float4*)Ks;
    const float4* QQ = (const float4*)Qs;
    const long obase = ((long)(n*LL + c*T)*HH + h)*MM + m;

    for (int i = 0; i < T; i++) {
        float vv = Vs[i*MM + m];
        float p = 0.0f;
        #pragma unroll
        for (int jj = 0; jj < 8; jj++) {
            float4 k4 = KK[i*16 + dh*8 + jj];
            float4 q4 = QQ[i*16 + dh*8 + jj];
            acc[jj*4+0] += k4.x * vv;  p += q4.x * acc[jj*4+0];
            acc[jj*4+1] += k4.y * vv;  p += q4.y * acc[jj*4+1];
            acc[jj*4+2] += k4.z * vv;  p += q4.z * acc[jj*4+2];
            acc[jj*4+3] += k4.w * vv;  p += q4.w * acc[jj*4+3];
        }
        // pair-reduce over the two d-halves (adjacent lanes)
        p += __shfl_xor_sync(0xffffffffu, p, 1);
        if (dh == 0)
            out[obase + (long)i*HH*MM] = p * zinv[i];
    }
}

// ---------------------------------------------------------------------------
extern "C" void kernel_launch(void* const* d_in, const int* in_sizes, int n_in,
                              void* d_out, int out_size)
{
    const float* queries = (const float*)d_in[0];
    const float* keys    = (const float*)d_in[1];
    const float* values  = (const float*)d_in[2];
    float* out = (float*)d_out;

    const int smem_scan = (16448 + 128) * (int)sizeof(float);  // ~66 KB
    // idempotent; safe to call per-launch (not a stream-ordered op)
    cudaFuncSetAttribute(scan_kernel,
                         cudaFuncAttributeMaxDynamicSharedMemorySize, smem_scan);

    chunk_sums_kernel<<<NBLK, 128>>>(keys, values);
    prefix_kernel<<<NH, 1024>>>();
    scan_kernel<<<NBLK, 128, smem_scan>>>(queries, keys, values, out);
}